// round 15
// baseline (speedup 1.0000x reference)
#include <cuda_runtime.h>
#include <cuda_bf16.h>
#include <math.h>
#include <stdint.h>

#define B_ 256
#define T_ 2048
#define C_ 12
#define K_ 4
#define L_ 8
#define FEAT_ 64
#define HID_ 128
#define NCLS_ 10
#define N2_ 1024
#define TR_ 1025
#define EPS_ 1e-5f
#define NBMAX_ 128

typedef unsigned long long ull;

__device__ float g_filt[K_ * TR_];
__device__ float d_modes[(size_t)K_ * B_ * C_ * T_];
__device__ float d_h1[(size_t)K_ * B_ * 32 * T_];
__device__ float d_h2[(size_t)K_ * B_ * 64 * T_];
__device__ float d_h3[(size_t)K_ * B_ * 64 * T_];
__device__ float d_psum[(size_t)K_ * 64 * B_ * NBMAX_];
__device__ float d_psq[(size_t)K_ * 64 * B_ * NBMAX_];
__device__ float d_mean[K_ * 64];
__device__ float d_rstd[K_ * 64];
__device__ float d_feats[B_ * K_ * FEAT_];
// mma weight images: [km][dk][half][co][ci padded to CINP] bf16 (hi,lo)
__device__ __align__(16) __nv_bfloat16 d_wimg1[K_ * 7 * 2 * 32 * 24];
__device__ __align__(16) __nv_bfloat16 d_wimg2[K_ * 5 * 2 * 64 * 40];
__device__ __align__(16) __nv_bfloat16 d_wimg3[K_ * 3 * 2 * 64 * 72];

__device__ __forceinline__ uint32_t smem_u32(const void* p) {
    uint32_t a;
    asm("{ .reg .u64 t; cvta.to.shared.u64 t, %1; cvt.u32.u64 %0, t; }" : "=r"(a) : "l"(p));
    return a;
}
__device__ __forceinline__ void ldsm4(uint32_t* a, uint32_t addr) {
    asm volatile("ldmatrix.sync.aligned.m8n8.x4.shared.b16 {%0,%1,%2,%3}, [%4];"
        : "=r"(a[0]), "=r"(a[1]), "=r"(a[2]), "=r"(a[3]) : "r"(addr));
}
__device__ __forceinline__ void mma16816(float* d, const uint32_t* a, const uint32_t* b) {
    asm volatile(
        "mma.sync.aligned.m16n8k16.row.col.f32.bf16.bf16.f32 "
        "{%0,%1,%2,%3}, {%4,%5,%6,%7}, {%8,%9}, {%0,%1,%2,%3};"
        : "+f"(d[0]), "+f"(d[1]), "+f"(d[2]), "+f"(d[3])
        : "r"(a[0]), "r"(a[1]), "r"(a[2]), "r"(a[3]), "r"(b[0]), "r"(b[1]));
}

// ---- 1. UVMD filters ----
__device__ __forceinline__ float softplusf(float x) {
    if (x > 20.f) return x;
    return log1pf(expf(x));
}
__global__ __launch_bounds__(128) void g_kernel(
        const float* __restrict__ la, const float* __restrict__ rt,
        const float* __restrict__ ro) {
    float om[K_];
#pragma unroll
    for (int k = 0; k < K_; k++) om[k] = 0.5f / (1.0f + expf(-ro[k]));
    int f = blockIdx.x * blockDim.x + threadIdx.x;
    if (f >= TR_) return;
    float fr = 0.5f * (float)f / 1024.0f;
    float u[K_] = {0.f, 0.f, 0.f, 0.f};
    float lam = 0.f;
    for (int l = 0; l < L_; l++) {
        float tau_l = softplusf(rt[l]);
        float us = u[0] + u[1] + u[2] + u[3];
        float nu[K_], ns = 0.f;
#pragma unroll
        for (int k = 0; k < K_; k++) {
            float a = expf(la[l * K_ + k]);
            float d = fr - om[k];
            nu[k] = (1.0f - (us - u[k]) + 0.5f * lam) / (1.0f + 2.0f * a * d * d);
            ns += nu[k];
        }
#pragma unroll
        for (int k = 0; k < K_; k++) u[k] = nu[k];
        lam += tau_l * (1.0f - ns);
    }
#pragma unroll
    for (int k = 0; k < K_; k++) g_filt[k * TR_ + f] = u[k];
}

// ---- 2. UVMD FFT ----
__device__ __forceinline__ void fft1024(float* zr, float* zi, const float* twr,
                                        const float* twi, float dir, int tid) {
#pragma unroll
    for (int s = 0; s < 10; s++) {
        int half = 1 << s, shift = 9 - s;
#pragma unroll
        for (int rep = 0; rep < 2; rep++) {
            int i = tid + rep * 256;
            int pos = i & (half - 1);
            int i1 = ((i >> s) << (s + 1)) + pos;
            int i2 = i1 + half;
            int ti = pos << shift;
            float c = twr[ti], sn = dir * twi[ti];
            float x2r = zr[i2], x2i = zi[i2];
            float tr = c * x2r - sn * x2i, tim = sn * x2r + c * x2i;
            float x1r = zr[i1], x1i = zi[i1];
            zr[i2] = x1r - tr; zi[i2] = x1i - tim;
            zr[i1] = x1r + tr; zi[i1] = x1i + tim;
        }
        __syncthreads();
    }
}
__global__ __launch_bounds__(256) void uvmd_kernel(const float* __restrict__ x) {
    __shared__ float twr[512], twi[512];
    __shared__ float zr[N2_], zi[N2_];
    __shared__ float Xr[TR_], Xi[TR_];
    int tid = threadIdx.x;
    int b = blockIdx.x / C_, c = blockIdx.x % C_;
    for (int j = tid; j < 512; j += 256) {
        float ang = (float)M_PI * (float)j / 512.0f;
        twr[j] = cosf(ang); twi[j] = -sinf(ang);
    }
    const float* xb = x + (size_t)b * T_ * C_ + c;
    for (int n = tid; n < N2_; n += 256) {
        int j = __brev((unsigned)n) >> 22;
        zr[n] = xb[(size_t)(2 * j) * C_];
        zi[n] = xb[(size_t)(2 * j + 1) * C_];
    }
    __syncthreads();
    fft1024(zr, zi, twr, twi, 1.0f, tid);
    for (int k = tid; k < N2_; k += 256) {
        if (k == 0) {
            Xr[0] = zr[0] + zi[0]; Xi[0] = 0.f;
            Xr[N2_] = zr[0] - zi[0]; Xi[N2_] = 0.f;
        } else {
            float ar = zr[k], ai = zi[k];
            float br = zr[N2_ - k], bi = -zi[N2_ - k];
            float er = 0.5f * (ar + br), ei = 0.5f * (ai + bi);
            float dr = 0.5f * (ar - br), di = 0.5f * (ai - bi);
            float or_ = di, oi = -dr, s_, c_;
            __sincosf(-(float)M_PI * (float)k / 1024.0f, &s_, &c_);
            Xr[k] = er + c_ * or_ - s_ * oi;
            Xi[k] = ei + s_ * or_ + c_ * oi;
        }
    }
    __syncthreads();
    const float invn = 1.0f / 1024.0f;
    for (int km = 0; km < K_; km++) {
        const float* g = g_filt + km * TR_;
        for (int n = tid; n < N2_; n += 256) {
            int k = __brev((unsigned)n) >> 22;
            float vr, vi;
            if (k == 0) {
                float y0 = g[0] * Xr[0], y1 = g[N2_] * Xr[N2_];
                vr = 0.5f * (y0 + y1); vi = 0.5f * (y0 - y1);
            } else {
                float gk = g[k], gm = g[N2_ - k];
                float yr = gk * Xr[k], yi = gk * Xi[k];
                float mr = gm * Xr[N2_ - k], mi = -(gm * Xi[N2_ - k]);
                float er = 0.5f * (yr + mr), ei = 0.5f * (yi + mi);
                float dr = 0.5f * (yr - mr), di = 0.5f * (yi - mi);
                float s_, c_;
                __sincosf((float)M_PI * (float)k / 1024.0f, &s_, &c_);
                vr = er - (s_ * dr + c_ * di);
                vi = ei + (c_ * dr - s_ * di);
            }
            zr[n] = vr; zi[n] = vi;
        }
        __syncthreads();
        fft1024(zr, zi, twr, twi, -1.0f, tid);
        float* orow = d_modes + ((((size_t)km * B_ + b) * C_ + c)) * T_;
        for (int n = tid; n < N2_; n += 256)
            *reinterpret_cast<float2*>(orow + 2 * n) =
                make_float2(zr[n] * invn, zi[n] * invn);
        __syncthreads();
    }
}

// ---- 2b. weight prep: hi/lo split, padded [km][dk][half][co][ciP] ----
template <int CIN, int KS, int CINP, int COUT>
__device__ __forceinline__ void wimg_one(const float* __restrict__ w,
                                         __nv_bfloat16* __restrict__ img, int i) {
    const int n = K_ * KS * 2 * COUT * CINP;
    if (i >= n) return;
    int ci = i % CINP;
    int r = i / CINP;
    int co = r % COUT; r /= COUT;
    int half = r % 2; r /= 2;
    int dk = r % KS;
    int km = r / KS;
    float f = (ci < CIN) ? w[(((size_t)km * COUT + co) * CIN + ci) * KS + dk] : 0.f;
    __nv_bfloat16 hi = __float2bfloat16(f);
    img[i] = half ? __float2bfloat16(f - __bfloat162float(hi)) : hi;
}
__global__ __launch_bounds__(256) void wprep_kernel(
    const float* __restrict__ w1, const float* __restrict__ w2,
    const float* __restrict__ w3) {
    int i = blockIdx.x * blockDim.x + threadIdx.x;
    wimg_one<12, 7, 24, 32>(w1, d_wimg1, i);
    wimg_one<32, 5, 40, 64>(w2, d_wimg2, i);
    wimg_one<64, 3, 72, 64>(w3, d_wimg3, i);
}

// ---- 3. conv via mma.sync bf16 hi/lo split; NT tiles per CTA ----
// Warp w owns t rows 16w..16w+15 x all COUT. B fragments (weights) load
// hi+lo halves in ONE ldmatrix.x4 (lanes 0-15 -> hi segment, 16-31 -> lo).
template <int CIN, int COUT, int KS, int NT, bool HASBN>
__global__ __launch_bounds__(256) void conv_mma_kernel(
    const float* __restrict__ in, const __nv_bfloat16* __restrict__ wimg,
    const float* __restrict__ bias,
    const float* __restrict__ bng, const float* __restrict__ bnb,
    float* __restrict__ out, float* __restrict__ psum, float* __restrict__ psq)
{
    constexpr int PAD = KS / 2, NROW = 136;
    constexpr int CIN16 = ((CIN + 15) / 16) * 16;
    constexpr int CINP = CIN16 + 8, ROWB = CINP * 2;
    constexpr int XB = NROW * ROWB, WSEG = COUT * ROWB;
    constexpr int OFF_XL = XB, OFF_W = 2 * XB;
    constexpr int STR = COUT + 5;
    constexpr int OFF_STG = OFF_W + KS * 2 * WSEG;
    constexpr int OFF_SA = OFF_STG + 8 * 8 * STR * 4;
    constexpr int NCC = CIN16 / 16, NFR = COUT / 8;
    constexpr int NBP = (16 / NT) * 8;       // stats partials per (co,b)
    extern __shared__ __align__(16) char smem[];
    uint32_t sb = smem_u32(smem);
    int tid = threadIdx.x, w = tid >> 5, lane = tid & 31;
    int b = blockIdx.y, km = blockIdx.z, bx = blockIdx.x;

    float* s_a = reinterpret_cast<float*>(smem + OFF_SA);
    float* s_c = s_a + CIN;
    if (HASBN) {
        for (int ci = tid; ci < CIN; ci += 256) {
            float a = bng[km * CIN + ci] * d_rstd[km * 64 + ci];
            s_a[ci] = a;
            s_c[ci] = bnb[km * CIN + ci] - a * d_mean[km * 64 + ci];
        }
    }
    {   // W copy once per CTA
        const uint4* src = reinterpret_cast<const uint4*>(
            reinterpret_cast<const char*>(wimg) + (size_t)km * KS * 2 * WSEG);
        uint4* dst = reinterpret_cast<uint4*>(smem + OFF_W);
        for (int i = tid; i < KS * 2 * WSEG / 16; i += 256) dst[i] = src[i];
    }
    __syncthreads();

    const float* inb = in + (((size_t)km * B_ + b) * CIN) * T_;
    float* outb = out + (((size_t)km * B_ + b) * COUT) * T_;
    int m0 = w * 16;
    uint32_t aoff = (uint32_t)((lane & 15) * ROWB + (lane >> 4) * 16);
    // B x4 lane map: lanes 0-15 hi half (2 matrices), lanes 16-31 lo (+WSEG)
    uint32_t boff = (uint32_t)((lane & 7) * ROWB + ((lane >> 3) & 1) * 16
                               + ((lane >> 4) ? WSEG : 0));
    int cbase = 2 * (lane & 3);
    float bb0[NFR], bb1[NFR];
#pragma unroll
    for (int j = 0; j < NFR; j++) {
        bb0[j] = __ldg(&bias[km * COUT + 8 * j + cbase]);
        bb1[j] = __ldg(&bias[km * COUT + 8 * j + cbase + 1]);
    }
    float sth0[NFR], sth1[NFR], qth0[NFR], qth1[NFR];
#pragma unroll
    for (int j = 0; j < NFR; j++) { sth0[j] = sth1[j] = qth0[j] = qth1[j] = 0.f; }

    for (int tile = 0; tile < NT; tile++) {
        int t0 = (bx * NT + tile) * 128;
        for (int idx = tid; idx < CIN16 * NROW; idx += 256) {
            int ci = idx / NROW, r = idx - ci * NROW;
            int t = t0 + r - PAD;
            float v = 0.f;
            if (ci < CIN && t >= 0 && t < T_) {
                v = inb[(size_t)ci * T_ + t];
                if (HASBN) v = fmaxf(fmaf(s_a[ci], v, s_c[ci]), 0.f);
            }
            __nv_bfloat16 hi = __float2bfloat16(v);
            __nv_bfloat16 lo = __float2bfloat16(v - __bfloat162float(hi));
            *reinterpret_cast<__nv_bfloat16*>(smem + r * ROWB + ci * 2) = hi;
            *reinterpret_cast<__nv_bfloat16*>(smem + OFF_XL + r * ROWB + ci * 2) = lo;
        }
        __syncthreads();

        float acc[NFR][4];
#pragma unroll
        for (int j = 0; j < NFR; j++)
#pragma unroll
            for (int p = 0; p < 4; p++) acc[j][p] = 0.f;
#pragma unroll
        for (int cc = 0; cc < NCC; cc++) {
#pragma unroll
            for (int dk = 0; dk < KS; dk++) {
                uint32_t ab = sb + (uint32_t)((m0 + dk) * ROWB + cc * 32) + aoff;
                uint32_t ah[4], al[4];
                ldsm4(ah, ab);
                ldsm4(al, ab + XB);
                uint32_t wbase = sb + OFF_W + (uint32_t)(dk * 2 * WSEG + cc * 32) + boff;
#pragma unroll
                for (int j = 0; j < NFR; j++) {
                    uint32_t bhl[4];         // {bh0, bh1, bl0, bl1}
                    ldsm4(bhl, wbase + j * 8 * ROWB);
                    mma16816(acc[j], ah, bhl);       // hi x hi
                    mma16816(acc[j], ah, bhl + 2);   // hi x lo
                    mma16816(acc[j], al, bhl);       // lo x hi
                }
            }
        }
        __syncthreads();

        float* sd = reinterpret_cast<float*>(smem + OFF_STG) + w * 8 * STR;
        int r = lane >> 2;
#pragma unroll
        for (int p = 0; p < 2; p++) {
#pragma unroll
            for (int j = 0; j < NFR; j++) {
                float v0 = acc[j][2 * p] + bb0[j];
                float v1 = acc[j][2 * p + 1] + bb1[j];
                sth0[j] += v0; sth1[j] += v1;
                qth0[j] += v0 * v0; qth1[j] += v1 * v1;
                sd[r * STR + 8 * j + cbase] = v0;
                sd[r * STR + 8 * j + cbase + 1] = v1;
            }
            __syncwarp();
            int tt = lane & 7, cop = lane >> 3;
#pragma unroll
            for (int co2 = 0; co2 < COUT; co2 += 4) {
                int co = co2 + cop;
                outb[(size_t)co * T_ + t0 + m0 + 8 * p + tt] = sd[tt * STR + co];
            }
            __syncwarp();
        }
    }

#pragma unroll
    for (int j = 0; j < NFR; j++) {
        float s0 = sth0[j], s1 = sth1[j], q0 = qth0[j], q1 = qth1[j];
#pragma unroll
        for (int o = 16; o >= 4; o >>= 1) {
            s0 += __shfl_down_sync(0xffffffffu, s0, o);
            s1 += __shfl_down_sync(0xffffffffu, s1, o);
            q0 += __shfl_down_sync(0xffffffffu, q0, o);
            q1 += __shfl_down_sync(0xffffffffu, q1, o);
        }
        if (lane < 4) {
            int co = 8 * j + 2 * lane;
            size_t pi = ((size_t)(km * COUT + co) * B_ + b) * NBP + bx * 8 + w;
            psum[pi] = s0; psq[pi] = q0;
            pi = ((size_t)(km * COUT + co + 1) * B_ + b) * NBP + bx * 8 + w;
            psum[pi] = s1; psq[pi] = q1;
        }
    }
}

// ---- 4. BN stats finalize ----
__global__ __launch_bounds__(256) void stats_fin_kernel(int Cout, int nblk) {
    int co = blockIdx.x, km = blockIdx.y, tid = threadIdx.x;
    const float* ps = d_psum + (size_t)(km * Cout + co) * B_ * nblk;
    const float* pq = d_psq + (size_t)(km * Cout + co) * B_ * nblk;
    float s = 0.f, q = 0.f;
    for (int i = tid; i < B_ * nblk; i += 256) { s += ps[i]; q += pq[i]; }
    __shared__ float r1[256], r2[256];
    r1[tid] = s; r2[tid] = q;
    __syncthreads();
    for (int o = 128; o > 0; o >>= 1) {
        if (tid < o) { r1[tid] += r1[tid + o]; r2[tid] += r2[tid + o]; }
        __syncthreads();
    }
    if (tid == 0) {
        float cnt = (float)B_ * (float)T_;
        float m = r1[0] / cnt;
        float v = r2[0] / cnt - m * m;
        d_mean[km * 64 + co] = m;
        d_rstd[km * 64 + co] = rsqrtf(v + EPS_);
    }
}

// ---- 5. pool ----
__global__ __launch_bounds__(256) void pool_kernel(
    const float* __restrict__ h, const float* __restrict__ bng,
    const float* __restrict__ bnb) {
    int co = blockIdx.x, b = blockIdx.y, km = blockIdx.z, tid = threadIdx.x;
    float a = bng[km * FEAT_ + co] * d_rstd[km * 64 + co];
    float cc = bnb[km * FEAT_ + co] - a * d_mean[km * 64 + co];
    const float* row = h + (((size_t)km * B_ + b) * FEAT_ + co) * T_;
    float s = 0.f;
    for (int t = tid; t < T_; t += 256)
        s += fmaxf(fmaf(a, row[t], cc), 0.f);
    __shared__ float r[256];
    r[tid] = s;
    __syncthreads();
    for (int o = 128; o > 0; o >>= 1) {
        if (tid < o) r[tid] += r[tid + o];
        __syncthreads();
    }
    if (tid == 0)
        d_feats[(size_t)b * (K_ * FEAT_) + km * FEAT_ + co] = r[0] * (1.0f / T_);
}

// ---- 6. classifier ----
__global__ __launch_bounds__(128) void classifier_kernel(
    const float* __restrict__ w1, const float* __restrict__ b1,
    const float* __restrict__ w2, const float* __restrict__ b2,
    float* __restrict__ out) {
    int b = blockIdx.x, j = threadIdx.x;
    __shared__ float sf[K_ * FEAT_];
    __shared__ float sh[HID_];
    for (int i = j; i < K_ * FEAT_; i += 128)
        sf[i] = d_feats[(size_t)b * (K_ * FEAT_) + i];
    __syncthreads();
    float a = b1[j];
    const float* wr = w1 + (size_t)j * (K_ * FEAT_);
#pragma unroll 8
    for (int i = 0; i < K_ * FEAT_; i++) a = fmaf(sf[i], wr[i], a);
    sh[j] = fmaxf(a, 0.f);
    __syncthreads();
    if (j < NCLS_) {
        float o = b2[j];
        const float* w2r = w2 + (size_t)j * HID_;
#pragma unroll 8
        for (int i = 0; i < HID_; i++) o = fmaf(sh[i], w2r[i], o);
        out[b * NCLS_ + j] = o;
    }
}

// ---- launch ----
extern "C" void kernel_launch(void* const* d_in, const int* in_sizes, int n_in,
                              void* d_out, int out_size) {
    const float* x         = (const float*)d_in[0];
    const float* log_alpha = (const float*)d_in[1];
    const float* raw_tau   = (const float*)d_in[2];
    const float* raw_omega = (const float*)d_in[3];
    const float* conv_w1   = (const float*)d_in[4];
    const float* conv_b1   = (const float*)d_in[5];
    const float* bn_g1     = (const float*)d_in[6];
    const float* bn_b1     = (const float*)d_in[7];
    const float* conv_w2   = (const float*)d_in[8];
    const float* conv_b2   = (const float*)d_in[9];
    const float* bn_g2     = (const float*)d_in[10];
    const float* bn_b2     = (const float*)d_in[11];
    const float* conv_w3   = (const float*)d_in[12];
    const float* conv_b3   = (const float*)d_in[13];
    const float* bn_g3     = (const float*)d_in[14];
    const float* bn_b3     = (const float*)d_in[15];
    const float* fc1_w     = (const float*)d_in[16];
    const float* fc1_b     = (const float*)d_in[17];
    const float* fc2_w     = (const float*)d_in[18];
    const float* fc2_b     = (const float*)d_in[19];
    float* out = (float*)d_out;

    float *p_modes, *p_h1, *p_h2, *p_h3, *p_psum, *p_psq;
    __nv_bfloat16 *p_wi1, *p_wi2, *p_wi3;
    cudaGetSymbolAddress((void**)&p_modes, d_modes);
    cudaGetSymbolAddress((void**)&p_h1, d_h1);
    cudaGetSymbolAddress((void**)&p_h2, d_h2);
    cudaGetSymbolAddress((void**)&p_h3, d_h3);
    cudaGetSymbolAddress((void**)&p_psum, d_psum);
    cudaGetSymbolAddress((void**)&p_psq, d_psq);
    cudaGetSymbolAddress((void**)&p_wi1, d_wimg1);
    cudaGetSymbolAddress((void**)&p_wi2, d_wimg2);
    cudaGetSymbolAddress((void**)&p_wi3, d_wimg3);

    const int smem1 = 2 * 136 * 48 + 7 * 2 * 32 * 48 + 8 * 8 * 37 * 4 + 128;
    const int smem2 = 2 * 136 * 80 + 5 * 2 * 64 * 80 + 8 * 8 * 69 * 4 + 256;
    const int smem3 = 2 * 136 * 144 + 3 * 2 * 64 * 144 + 8 * 8 * 69 * 4 + 512;
    cudaFuncSetAttribute((const void*)conv_mma_kernel<12, 32, 7, 8, false>,
                         cudaFuncAttributeMaxDynamicSharedMemorySize, smem1);
    cudaFuncSetAttribute((const void*)conv_mma_kernel<32, 64, 5, 8, true>,
                         cudaFuncAttributeMaxDynamicSharedMemorySize, smem2);
    cudaFuncSetAttribute((const void*)conv_mma_kernel<64, 64, 3, 8, true>,
                         cudaFuncAttributeMaxDynamicSharedMemorySize, smem3);

    // #1 filters, #2 wprep, #3 wprep again (idempotent filler so that the
    // ncu capture slot -- launch position 4 -- lands on uvmd_kernel)
    g_kernel<<<(TR_ + 127) / 128, 128>>>(log_alpha, raw_tau, raw_omega);
    wprep_kernel<<<(K_ * 3 * 2 * 64 * 72 + 255) / 256, 256>>>(conv_w1, conv_w2, conv_w3);
    wprep_kernel<<<(K_ * 3 * 2 * 64 * 72 + 255) / 256, 256>>>(conv_w1, conv_w2, conv_w3);
    // #4 UVMD  <-- ncu capture target this round
    uvmd_kernel<<<B_ * C_, 256>>>(x);

    conv_mma_kernel<12, 32, 7, 8, false><<<dim3(2, B_, K_), 256, smem1>>>(
        p_modes, p_wi1, conv_b1, nullptr, nullptr, p_h1, p_psum, p_psq);
    stats_fin_kernel<<<dim3(32, K_), 256>>>(32, 16);
    conv_mma_kernel<32, 64, 5, 8, true><<<dim3(2, B_, K_), 256, smem2>>>(
        p_h1, p_wi2, conv_b2, bn_g1, bn_b1, p_h2, p_psum, p_psq);
    stats_fin_kernel<<<dim3(64, K_), 256>>>(64, 16);
    conv_mma_kernel<64, 64, 3, 8, true><<<dim3(2, B_, K_), 256, smem3>>>(
        p_h2, p_wi3, conv_b3, bn_g2, bn_b2, p_h3, p_psum, p_psq);
    stats_fin_kernel<<<dim3(64, K_), 256>>>(64, 16);
    pool_kernel<<<dim3(FEAT_, B_, K_), 256>>>(p_h3, bn_g3, bn_b3);
    classifier_kernel<<<B_, HID_>>>(fc1_w, fc1_b, fc2_w, fc2_b, out);
}

// round 17
// speedup vs baseline: 1.4113x; 1.4113x over previous
#include <cuda_runtime.h>
#include <cuda_bf16.h>
#include <math.h>
#include <stdint.h>

#define B_ 256
#define T_ 2048
#define C_ 12
#define K_ 4
#define L_ 8
#define FEAT_ 64
#define HID_ 128
#define NCLS_ 10
#define N2_ 1024
#define TR_ 1025
#define EPS_ 1e-5f
#define NBMAX_ 128

typedef unsigned long long ull;

__device__ float g_filt[K_ * TR_];
__device__ float d_modes[(size_t)K_ * B_ * C_ * T_];
__device__ float d_h1[(size_t)K_ * B_ * 32 * T_];
__device__ float d_h2[(size_t)K_ * B_ * 64 * T_];
__device__ float d_h3[(size_t)K_ * B_ * 64 * T_];
__device__ float d_psum[(size_t)K_ * 64 * B_ * NBMAX_];
__device__ float d_psq[(size_t)K_ * 64 * B_ * NBMAX_];
__device__ float d_mean[K_ * 64];
__device__ float d_rstd[K_ * 64];
__device__ float d_feats[B_ * K_ * FEAT_];
// mma weight images: [km][dk][half][co][ci padded to CINP] bf16 (hi,lo)
__device__ __align__(16) __nv_bfloat16 d_wimg1[K_ * 7 * 2 * 32 * 24];
__device__ __align__(16) __nv_bfloat16 d_wimg2[K_ * 5 * 2 * 64 * 40];
__device__ __align__(16) __nv_bfloat16 d_wimg3[K_ * 3 * 2 * 64 * 72];

__device__ __forceinline__ uint32_t smem_u32(const void* p) {
    uint32_t a;
    asm("{ .reg .u64 t; cvta.to.shared.u64 t, %1; cvt.u32.u64 %0, t; }" : "=r"(a) : "l"(p));
    return a;
}
__device__ __forceinline__ void ldsm4(uint32_t* a, uint32_t addr) {
    asm volatile("ldmatrix.sync.aligned.m8n8.x4.shared.b16 {%0,%1,%2,%3}, [%4];"
        : "=r"(a[0]), "=r"(a[1]), "=r"(a[2]), "=r"(a[3]) : "r"(addr));
}
__device__ __forceinline__ void ldsm2(uint32_t* b, uint32_t addr) {
    asm volatile("ldmatrix.sync.aligned.m8n8.x2.shared.b16 {%0,%1}, [%2];"
        : "=r"(b[0]), "=r"(b[1]) : "r"(addr));
}
__device__ __forceinline__ void mma16816(float* d, const uint32_t* a, const uint32_t* b) {
    asm volatile(
        "mma.sync.aligned.m16n8k16.row.col.f32.bf16.bf16.f32 "
        "{%0,%1,%2,%3}, {%4,%5,%6,%7}, {%8,%9}, {%0,%1,%2,%3};"
        : "+f"(d[0]), "+f"(d[1]), "+f"(d[2]), "+f"(d[3])
        : "r"(a[0]), "r"(a[1]), "r"(a[2]), "r"(a[3]), "r"(b[0]), "r"(b[1]));
}

// ---- 1. UVMD filters ----
__device__ __forceinline__ float softplusf(float x) {
    if (x > 20.f) return x;
    return log1pf(expf(x));
}
__global__ __launch_bounds__(128) void g_kernel(
        const float* __restrict__ la, const float* __restrict__ rt,
        const float* __restrict__ ro) {
    float om[K_];
#pragma unroll
    for (int k = 0; k < K_; k++) om[k] = 0.5f / (1.0f + expf(-ro[k]));
    int f = blockIdx.x * blockDim.x + threadIdx.x;
    if (f >= TR_) return;
    float fr = 0.5f * (float)f / 1024.0f;
    float u[K_] = {0.f, 0.f, 0.f, 0.f};
    float lam = 0.f;
    for (int l = 0; l < L_; l++) {
        float tau_l = softplusf(rt[l]);
        float us = u[0] + u[1] + u[2] + u[3];
        float nu[K_], ns = 0.f;
#pragma unroll
        for (int k = 0; k < K_; k++) {
            float a = expf(la[l * K_ + k]);
            float d = fr - om[k];
            nu[k] = (1.0f - (us - u[k]) + 0.5f * lam) / (1.0f + 2.0f * a * d * d);
            ns += nu[k];
        }
#pragma unroll
        for (int k = 0; k < K_; k++) u[k] = nu[k];
        lam += tau_l * (1.0f - ns);
    }
#pragma unroll
    for (int k = 0; k < K_; k++) g_filt[k * TR_ + f] = u[k];
}

// ---- 2. UVMD FFT (float2-interleaved: LDS.64/STS.64 butterflies) ----
__device__ __forceinline__ void fft1024v(float2* z, const float2* tw,
                                         float dir, int tid) {
#pragma unroll
    for (int s = 0; s < 10; s++) {
        int half = 1 << s, shift = 9 - s;
#pragma unroll
        for (int rep = 0; rep < 2; rep++) {
            int i = tid + rep * 256;
            int pos = i & (half - 1);
            int i1 = ((i >> s) << (s + 1)) + pos;
            int i2 = i1 + half;
            float2 wv = tw[pos << shift];
            float c = wv.x, sn = dir * wv.y;
            float2 x2 = z[i2];
            float tr = c * x2.x - sn * x2.y, tim = sn * x2.x + c * x2.y;
            float2 x1 = z[i1];
            z[i2] = make_float2(x1.x - tr, x1.y - tim);
            z[i1] = make_float2(x1.x + tr, x1.y + tim);
        }
        __syncthreads();
    }
}
__global__ __launch_bounds__(256) void uvmd_kernel(const float* __restrict__ x) {
    __shared__ float2 tw[512];
    __shared__ float2 z[N2_];
    __shared__ float Xr[TR_], Xi[TR_];
    int tid = threadIdx.x;
    int b = blockIdx.x / C_, c = blockIdx.x % C_;
    for (int j = tid; j < 512; j += 256) {
        float ang = (float)M_PI * (float)j / 512.0f;
        tw[j] = make_float2(cosf(ang), -sinf(ang));
    }
    const float* xb = x + (size_t)b * T_ * C_ + c;
    for (int n = tid; n < N2_; n += 256) {
        int j = __brev((unsigned)n) >> 22;
        z[n] = make_float2(xb[(size_t)(2 * j) * C_], xb[(size_t)(2 * j + 1) * C_]);
    }
    __syncthreads();
    fft1024v(z, tw, 1.0f, tid);
    for (int k = tid; k < N2_; k += 256) {
        if (k == 0) {
            Xr[0] = z[0].x + z[0].y; Xi[0] = 0.f;
            Xr[N2_] = z[0].x - z[0].y; Xi[N2_] = 0.f;
        } else {
            float ar = z[k].x, ai = z[k].y;
            float br = z[N2_ - k].x, bi = -z[N2_ - k].y;
            float er = 0.5f * (ar + br), ei = 0.5f * (ai + bi);
            float dr = 0.5f * (ar - br), di = 0.5f * (ai - bi);
            float or_ = di, oi = -dr, s_, c_;
            __sincosf(-(float)M_PI * (float)k / 1024.0f, &s_, &c_);
            Xr[k] = er + c_ * or_ - s_ * oi;
            Xi[k] = ei + s_ * or_ + c_ * oi;
        }
    }
    __syncthreads();
    const float invn = 1.0f / 1024.0f;
    for (int km = 0; km < K_; km++) {
        const float* g = g_filt + km * TR_;
        for (int n = tid; n < N2_; n += 256) {
            int k = __brev((unsigned)n) >> 22;
            float vr, vi;
            if (k == 0) {
                float y0 = g[0] * Xr[0], y1 = g[N2_] * Xr[N2_];
                vr = 0.5f * (y0 + y1); vi = 0.5f * (y0 - y1);
            } else {
                float gk = g[k], gm = g[N2_ - k];
                float yr = gk * Xr[k], yi = gk * Xi[k];
                float mr = gm * Xr[N2_ - k], mi = -(gm * Xi[N2_ - k]);
                float er = 0.5f * (yr + mr), ei = 0.5f * (yi + mi);
                float dr = 0.5f * (yr - mr), di = 0.5f * (yi - mi);
                float s_, c_;
                __sincosf((float)M_PI * (float)k / 1024.0f, &s_, &c_);
                vr = er - (s_ * dr + c_ * di);
                vi = ei + (c_ * dr - s_ * di);
            }
            z[n] = make_float2(vr, vi);
        }
        __syncthreads();
        fft1024v(z, tw, -1.0f, tid);
        float* orow = d_modes + ((((size_t)km * B_ + b) * C_ + c)) * T_;
        for (int n = tid; n < N2_; n += 256) {
            float2 v = z[n];
            *reinterpret_cast<float2*>(orow + 2 * n) =
                make_float2(v.x * invn, v.y * invn);
        }
        __syncthreads();
    }
}

// ---- 2b. weight prep: hi/lo split, padded [km][dk][half][co][ciP] ----
template <int CIN, int KS, int CINP, int COUT>
__device__ __forceinline__ void wimg_one(const float* __restrict__ w,
                                         __nv_bfloat16* __restrict__ img, int i) {
    const int n = K_ * KS * 2 * COUT * CINP;
    if (i >= n) return;
    int ci = i % CINP;
    int r = i / CINP;
    int co = r % COUT; r /= COUT;
    int half = r % 2; r /= 2;
    int dk = r % KS;
    int km = r / KS;
    float f = (ci < CIN) ? w[(((size_t)km * COUT + co) * CIN + ci) * KS + dk] : 0.f;
    __nv_bfloat16 hi = __float2bfloat16(f);
    img[i] = half ? __float2bfloat16(f - __bfloat162float(hi)) : hi;
}
__global__ __launch_bounds__(256) void wprep_kernel(
    const float* __restrict__ w1, const float* __restrict__ w2,
    const float* __restrict__ w3) {
    int i = blockIdx.x * blockDim.x + threadIdx.x;
    wimg_one<12, 7, 24, 32>(w1, d_wimg1, i);
    wimg_one<32, 5, 40, 64>(w2, d_wimg2, i);
    wimg_one<64, 3, 72, 64>(w3, d_wimg3, i);
}

// ---- 3. conv via mma.sync bf16 hi/lo split; NT tiles per CTA (r14-proven) ----
template <int CIN, int COUT, int KS, int NT, bool HASBN>
__global__ __launch_bounds__(256) void conv_mma_kernel(
    const float* __restrict__ in, const __nv_bfloat16* __restrict__ wimg,
    const float* __restrict__ bias,
    const float* __restrict__ bng, const float* __restrict__ bnb,
    float* __restrict__ out, float* __restrict__ psum, float* __restrict__ psq)
{
    constexpr int PAD = KS / 2, NROW = 136;
    constexpr int CIN16 = ((CIN + 15) / 16) * 16;
    constexpr int CINP = CIN16 + 8, ROWB = CINP * 2;
    constexpr int XB = NROW * ROWB, WSEG = COUT * ROWB;
    constexpr int OFF_XL = XB, OFF_W = 2 * XB;
    constexpr int STR = COUT + 5;
    constexpr int OFF_STG = OFF_W + KS * 2 * WSEG;
    constexpr int OFF_SA = OFF_STG + 8 * 8 * STR * 4;
    constexpr int NCC = CIN16 / 16, NFR = COUT / 8;
    constexpr int NBP = (16 / NT) * 8;
    extern __shared__ __align__(16) char smem[];
    uint32_t sb = smem_u32(smem);
    int tid = threadIdx.x, w = tid >> 5, lane = tid & 31;
    int b = blockIdx.y, km = blockIdx.z, bx = blockIdx.x;

    float* s_a = reinterpret_cast<float*>(smem + OFF_SA);
    float* s_c = s_a + CIN;
    if (HASBN) {
        for (int ci = tid; ci < CIN; ci += 256) {
            float a = bng[km * CIN + ci] * d_rstd[km * 64 + ci];
            s_a[ci] = a;
            s_c[ci] = bnb[km * CIN + ci] - a * d_mean[km * 64 + ci];
        }
    }
    {
        const uint4* src = reinterpret_cast<const uint4*>(
            reinterpret_cast<const char*>(wimg) + (size_t)km * KS * 2 * WSEG);
        uint4* dst = reinterpret_cast<uint4*>(smem + OFF_W);
        for (int i = tid; i < KS * 2 * WSEG / 16; i += 256) dst[i] = src[i];
    }
    __syncthreads();

    const float* inb = in + (((size_t)km * B_ + b) * CIN) * T_;
    float* outb = out + (((size_t)km * B_ + b) * COUT) * T_;
    int m0 = w * 16;
    uint32_t aoff = (uint32_t)((lane & 15) * ROWB + (lane >> 4) * 16);
    uint32_t boff = (uint32_t)((lane & 7) * ROWB + ((lane >> 3) & 1) * 16);
    int cbase = 2 * (lane & 3);
    float bb0[NFR], bb1[NFR];
#pragma unroll
    for (int j = 0; j < NFR; j++) {
        bb0[j] = __ldg(&bias[km * COUT + 8 * j + cbase]);
        bb1[j] = __ldg(&bias[km * COUT + 8 * j + cbase + 1]);
    }
    float sth0[NFR], sth1[NFR], qth0[NFR], qth1[NFR];
#pragma unroll
    for (int j = 0; j < NFR; j++) { sth0[j] = sth1[j] = qth0[j] = qth1[j] = 0.f; }

    for (int tile = 0; tile < NT; tile++) {
        int t0 = (bx * NT + tile) * 128;
        for (int idx = tid; idx < CIN16 * NROW; idx += 256) {
            int ci = idx / NROW, r = idx - ci * NROW;
            int t = t0 + r - PAD;
            float v = 0.f;
            if (ci < CIN && t >= 0 && t < T_) {
                v = inb[(size_t)ci * T_ + t];
                if (HASBN) v = fmaxf(fmaf(s_a[ci], v, s_c[ci]), 0.f);
            }
            __nv_bfloat16 hi = __float2bfloat16(v);
            __nv_bfloat16 lo = __float2bfloat16(v - __bfloat162float(hi));
            *reinterpret_cast<__nv_bfloat16*>(smem + r * ROWB + ci * 2) = hi;
            *reinterpret_cast<__nv_bfloat16*>(smem + OFF_XL + r * ROWB + ci * 2) = lo;
        }
        __syncthreads();

        float acc[NFR][4];
#pragma unroll
        for (int j = 0; j < NFR; j++)
#pragma unroll
            for (int p = 0; p < 4; p++) acc[j][p] = 0.f;
#pragma unroll
        for (int cc = 0; cc < NCC; cc++) {
#pragma unroll
            for (int dk = 0; dk < KS; dk++) {
                uint32_t ab = sb + (uint32_t)((m0 + dk) * ROWB + cc * 32) + aoff;
                uint32_t ah[4], al[4];
                ldsm4(ah, ab);
                ldsm4(al, ab + XB);
                uint32_t wbase = sb + OFF_W + (uint32_t)(dk * 2 * WSEG + cc * 32) + boff;
#pragma unroll
                for (int j = 0; j < NFR; j++) {
                    uint32_t bh[2], bl[2];
                    ldsm2(bh, wbase + j * 8 * ROWB);
                    ldsm2(bl, wbase + WSEG + j * 8 * ROWB);
                    mma16816(acc[j], ah, bh);
                    mma16816(acc[j], ah, bl);
                    mma16816(acc[j], al, bh);
                }
            }
        }
        __syncthreads();

        float* sd = reinterpret_cast<float*>(smem + OFF_STG) + w * 8 * STR;
        int r = lane >> 2;
#pragma unroll
        for (int p = 0; p < 2; p++) {
#pragma unroll
            for (int j = 0; j < NFR; j++) {
                float v0 = acc[j][2 * p] + bb0[j];
                float v1 = acc[j][2 * p + 1] + bb1[j];
                sth0[j] += v0; sth1[j] += v1;
                qth0[j] += v0 * v0; qth1[j] += v1 * v1;
                sd[r * STR + 8 * j + cbase] = v0;
                sd[r * STR + 8 * j + cbase + 1] = v1;
            }
            __syncwarp();
            int tt = lane & 7, cop = lane >> 3;
#pragma unroll
            for (int co2 = 0; co2 < COUT; co2 += 4) {
                int co = co2 + cop;
                outb[(size_t)co * T_ + t0 + m0 + 8 * p + tt] = sd[tt * STR + co];
            }
            __syncwarp();
        }
    }

#pragma unroll
    for (int j = 0; j < NFR; j++) {
        float s0 = sth0[j], s1 = sth1[j], q0 = qth0[j], q1 = qth1[j];
#pragma unroll
        for (int o = 16; o >= 4; o >>= 1) {
            s0 += __shfl_down_sync(0xffffffffu, s0, o);
            s1 += __shfl_down_sync(0xffffffffu, s1, o);
            q0 += __shfl_down_sync(0xffffffffu, q0, o);
            q1 += __shfl_down_sync(0xffffffffu, q1, o);
        }
        if (lane < 4) {
            int co = 8 * j + 2 * lane;
            size_t pi = ((size_t)(km * COUT + co) * B_ + b) * NBP + bx * 8 + w;
            psum[pi] = s0; psq[pi] = q0;
            pi = ((size_t)(km * COUT + co + 1) * B_ + b) * NBP + bx * 8 + w;
            psum[pi] = s1; psq[pi] = q1;
        }
    }
}

// ---- 4. BN stats finalize ----
__global__ __launch_bounds__(256) void stats_fin_kernel(int Cout, int nblk) {
    int co = blockIdx.x, km = blockIdx.y, tid = threadIdx.x;
    const float* ps = d_psum + (size_t)(km * Cout + co) * B_ * nblk;
    const float* pq = d_psq + (size_t)(km * Cout + co) * B_ * nblk;
    float s = 0.f, q = 0.f;
    for (int i = tid; i < B_ * nblk; i += 256) { s += ps[i]; q += pq[i]; }
    __shared__ float r1[256], r2[256];
    r1[tid] = s; r2[tid] = q;
    __syncthreads();
    for (int o = 128; o > 0; o >>= 1) {
        if (tid < o) { r1[tid] += r1[tid + o]; r2[tid] += r2[tid + o]; }
        __syncthreads();
    }
    if (tid == 0) {
        float cnt = (float)B_ * (float)T_;
        float m = r1[0] / cnt;
        float v = r2[0] / cnt - m * m;
        d_mean[km * 64 + co] = m;
        d_rstd[km * 64 + co] = rsqrtf(v + EPS_);
    }
}

// ---- 5. pool: warp-per-channel, shfl-only reduction ----
__global__ __launch_bounds__(256) void pool_kernel(
    const float* __restrict__ h, const float* __restrict__ bng,
    const float* __restrict__ bnb) {
    int w = threadIdx.x >> 5, lane = threadIdx.x & 31;
    int b = blockIdx.y, km = blockIdx.z;
    int co = blockIdx.x * 8 + w;
    float a = bng[km * FEAT_ + co] * d_rstd[km * 64 + co];
    float cc = bnb[km * FEAT_ + co] - a * d_mean[km * 64 + co];
    const float* row = h + (((size_t)km * B_ + b) * FEAT_ + co) * T_;
    float s = 0.f;
#pragma unroll 8
    for (int t = lane; t < T_; t += 32)
        s += fmaxf(fmaf(a, row[t], cc), 0.f);
#pragma unroll
    for (int o = 16; o > 0; o >>= 1)
        s += __shfl_down_sync(0xffffffffu, s, o);
    if (lane == 0)
        d_feats[(size_t)b * (K_ * FEAT_) + km * FEAT_ + co] = s * (1.0f / T_);
}

// ---- 6. classifier ----
__global__ __launch_bounds__(128) void classifier_kernel(
    const float* __restrict__ w1, const float* __restrict__ b1,
    const float* __restrict__ w2, const float* __restrict__ b2,
    float* __restrict__ out) {
    int b = blockIdx.x, j = threadIdx.x;
    __shared__ float sf[K_ * FEAT_];
    __shared__ float sh[HID_];
    for (int i = j; i < K_ * FEAT_; i += 128)
        sf[i] = d_feats[(size_t)b * (K_ * FEAT_) + i];
    __syncthreads();
    float a = b1[j];
    const float* wr = w1 + (size_t)j * (K_ * FEAT_);
#pragma unroll 8
    for (int i = 0; i < K_ * FEAT_; i++) a = fmaf(sf[i], wr[i], a);
    sh[j] = fmaxf(a, 0.f);
    __syncthreads();
    if (j < NCLS_) {
        float o = b2[j];
        const float* w2r = w2 + (size_t)j * HID_;
#pragma unroll 8
        for (int i = 0; i < HID_; i++) o = fmaf(sh[i], w2r[i], o);
        out[b * NCLS_ + j] = o;
    }
}

// ---- launch ----
extern "C" void kernel_launch(void* const* d_in, const int* in_sizes, int n_in,
                              void* d_out, int out_size) {
    const float* x         = (const float*)d_in[0];
    const float* log_alpha = (const float*)d_in[1];
    const float* raw_tau   = (const float*)d_in[2];
    const float* raw_omega = (const float*)d_in[3];
    const float* conv_w1   = (const float*)d_in[4];
    const float* conv_b1   = (const float*)d_in[5];
    const float* bn_g1     = (const float*)d_in[6];
    const float* bn_b1     = (const float*)d_in[7];
    const float* conv_w2   = (const float*)d_in[8];
    const float* conv_b2   = (const float*)d_in[9];
    const float* bn_g2     = (const float*)d_in[10];
    const float* bn_b2     = (const float*)d_in[11];
    const float* conv_w3   = (const float*)d_in[12];
    const float* conv_b3   = (const float*)d_in[13];
    const float* bn_g3     = (const float*)d_in[14];
    const float* bn_b3     = (const float*)d_in[15];
    const float* fc1_w     = (const float*)d_in[16];
    const float* fc1_b     = (const float*)d_in[17];
    const float* fc2_w     = (const float*)d_in[18];
    const float* fc2_b     = (const float*)d_in[19];
    float* out = (float*)d_out;

    float *p_modes, *p_h1, *p_h2, *p_h3, *p_psum, *p_psq;
    __nv_bfloat16 *p_wi1, *p_wi2, *p_wi3;
    cudaGetSymbolAddress((void**)&p_modes, d_modes);
    cudaGetSymbolAddress((void**)&p_h1, d_h1);
    cudaGetSymbolAddress((void**)&p_h2, d_h2);
    cudaGetSymbolAddress((void**)&p_h3, d_h3);
    cudaGetSymbolAddress((void**)&p_psum, d_psum);
    cudaGetSymbolAddress((void**)&p_psq, d_psq);
    cudaGetSymbolAddress((void**)&p_wi1, d_wimg1);
    cudaGetSymbolAddress((void**)&p_wi2, d_wimg2);
    cudaGetSymbolAddress((void**)&p_wi3, d_wimg3);

    const int smem1 = 2 * 136 * 48 + 7 * 2 * 32 * 48 + 8 * 8 * 37 * 4 + 128;
    const int smem2 = 2 * 136 * 80 + 5 * 2 * 64 * 80 + 8 * 8 * 69 * 4 + 256;
    const int smem3 = 2 * 136 * 144 + 3 * 2 * 64 * 144 + 8 * 8 * 69 * 4 + 512;
    cudaFuncSetAttribute((const void*)conv_mma_kernel<12, 32, 7, 8, false>,
                         cudaFuncAttributeMaxDynamicSharedMemorySize, smem1);
    cudaFuncSetAttribute((const void*)conv_mma_kernel<32, 64, 5, 8, true>,
                         cudaFuncAttributeMaxDynamicSharedMemorySize, smem2);
    cudaFuncSetAttribute((const void*)conv_mma_kernel<64, 64, 3, 8, true>,
                         cudaFuncAttributeMaxDynamicSharedMemorySize, smem3);

    // #1 filters, #2 wprep, #3 wprep (idempotent; keeps ncu slot #4 = uvmd)
    g_kernel<<<(TR_ + 127) / 128, 128>>>(log_alpha, raw_tau, raw_omega);
    wprep_kernel<<<(K_ * 3 * 2 * 64 * 72 + 255) / 256, 256>>>(conv_w1, conv_w2, conv_w3);
    wprep_kernel<<<(K_ * 3 * 2 * 64 * 72 + 255) / 256, 256>>>(conv_w1, conv_w2, conv_w3);
    // #4 UVMD (float2 FFT)  <-- ncu capture target
    uvmd_kernel<<<B_ * C_, 256>>>(x);

    conv_mma_kernel<12, 32, 7, 8, false><<<dim3(2, B_, K_), 256, smem1>>>(
        p_modes, p_wi1, conv_b1, nullptr, nullptr, p_h1, p_psum, p_psq);
    stats_fin_kernel<<<dim3(32, K_), 256>>>(32, 16);
    conv_mma_kernel<32, 64, 5, 8, true><<<dim3(2, B_, K_), 256, smem2>>>(
        p_h1, p_wi2, conv_b2, bn_g1, bn_b1, p_h2, p_psum, p_psq);
    stats_fin_kernel<<<dim3(64, K_), 256>>>(64, 16);
    conv_mma_kernel<64, 64, 3, 8, true><<<dim3(2, B_, K_), 256, smem3>>>(
        p_h2, p_wi3, conv_b3, bn_g2, bn_b2, p_h3, p_psum, p_psq);
    stats_fin_kernel<<<dim3(64, K_), 256>>>(64, 16);
    pool_kernel<<<dim3(FEAT_ / 8, B_, K_), 256>>>(p_h3, bn_g3, bn_b3);
    classifier_kernel<<<B_, HID_>>>(fc1_w, fc1_b, fc2_w, fc2_b, out);
}